// round 12
// baseline (speedup 1.0000x reference)
#include <cuda_runtime.h>
#include <stdint.h>

// Problem shape (fixed by the dataset)
#define BATCH   8192
#define IN_DIM  4096
#define N_RULES 2048
#define KWORDS  128              // u32 bit-words along k
#define NBG     8                // big rule-groups (256 rules each)
#define NPACK   1024             // pack tiles: 8 bg x 128 w-layers (group-major)
#define NOUT    1024             // out tiles:  64 rg32 x 16 row-slices
#define GRID    444              // 148 SMs x 3 CTAs -> all resident in wave 1

// Scratch (device globals — no allocation allowed)
__device__ uint32_t g_wbitsT[KWORDS * N_RULES];   // TRANSPOSED: [w][r]
__device__ unsigned g_done[NBG];                  // packed tiles per big group
                                                  // (zeroed by reset_kernel)

// Rare path: recompute out[b,r] DIRECTLY from x and wbitsT. res > 0 iff some
// k has W-bit set AND x[b,k] != 1.0f. Exits on the first such k (~1 x-load
// per call on typical inputs). No abits/aflag/pack_x needed anywhere.
__device__ __noinline__ float conj_direct(const float* __restrict__ x,
                                          int b, int r) {
    const float* xb = x + (size_t)b * IN_DIM;
    for (int i = 0; i < KWORDS; i++) {
        uint32_t wd = __ldcg(&g_wbitsT[(size_t)i * N_RULES + r]);
        while (wd) {
            int j = __ffs(wd) - 1;
            if (xb[i * 32 + j] != 1.0f) return 0.0f;
            wd &= wd - 1;
        }
    }
    return 1.0f;
}

// ---------------------------------------------------------------------------
// Fused persistent kernel, TWO item classes over a grid-stride loop:
//   ids [0, 1024):    pack tile (bg = id>>7, w-layer = id&127)  — never waits
//   ids [1024, 2048): out tile  (bg = q>>7; rg32 = bg*8+(q&7); slice = q>>3&15)
//                     — waits only on g_done[bg] == 128 (strictly earlier ids)
// Every CTA's id sequence is increasing, so all of a CTA's pack items precede
// its out items -> pack always progresses -> no deadlock, real overlap of the
// 32MB DRAM read stream (pack) with the 64MB L2 write stream (out).
// ---------------------------------------------------------------------------
__global__ void __launch_bounds__(256, 3)
fused_kernel(const float* __restrict__ W, const float* __restrict__ x,
             float* __restrict__ out) {
    __shared__ uint32_t sm[32 * 64];           // pack: bool-byte tile (8KB)
    uint32_t* sm_red = sm;                     // out: [8][32] partial folds
    uint32_t* s_w    = sm + 256;               // out: folded wany per rule
    float*    s_val  = (float*)(sm + 288);     // out: aflag==0 answer (16B-al.)
    uint32_t* s_flag = sm + 320;
    int tid = threadIdx.x;

    for (int p = blockIdx.x; p < NPACK + NOUT; p += GRID) {
        __syncthreads();                       // smem reuse guard between items
        if (p < NPACK) {
            // ---------------- pack tile: 32 k-rows x 256 rules ----------------
            int bg = p >> 7;                   // big group (256 rules)
            int w  = p & 127;                  // w-layer
            const float4* W4 = reinterpret_cast<const float4*>(W);
            size_t base = (size_t)(w * 32) * (N_RULES / 4) + bg * 64;
#pragma unroll
            for (int u = 0; u < 8; u++) {      // 8 independent coalesced loads
                int fi  = u * 256 + tid;
                int row = fi >> 6;
                int c4  = fi & 63;
                float4 v = W4[base + (size_t)row * (N_RULES / 4) + c4];
                uint32_t bb = (v.x > 0.5f ? 0x01u : 0u) |
                              (v.y > 0.5f ? 0x0100u : 0u) |
                              (v.z > 0.5f ? 0x010000u : 0u) |
                              (v.w > 0.5f ? 0x01000000u : 0u);
                sm[row * 64 + c4] = bb;
            }
            __syncthreads();
            const uint8_t* sm8 = reinterpret_cast<const uint8_t*>(sm);
            uint32_t word = 0;
#pragma unroll
            for (int j = 0; j < 32; j++)
                word |= (uint32_t)(sm8[j * 256 + tid] & 1u) << j;
            g_wbitsT[(size_t)w * N_RULES + bg * 256 + tid] = word;
            __threadfence();                   // release stores
            __syncthreads();
            if (tid == 0) atomicAdd(&g_done[bg], 1u);
        } else {
            // ---------------- out tile: 32 rules x 512 rows -------------------
            int q     = p - NPACK;
            int bg    = q >> 7;
            int rg    = bg * 8 + (q & 7);      // 32-rule group [0, 64)
            int slice = (q >> 3) & 15;
            int b0    = slice * 512;

            if (tid == 0) {                    // acquire group's pack tiles
                while (((volatile unsigned*)g_done)[bg] < 128u) __nanosleep(32);
                __threadfence();
            }
            __syncthreads();

            {   // fold wany for 32 rules over 128 w-layers (L2-resident 16KB)
                int r  = rg * 32 + (tid & 31);
                int wc = tid >> 5;             // 0..7
                uint32_t o = 0;
#pragma unroll
                for (int i = 0; i < 16; i++)
                    o |= __ldcg(&g_wbitsT[(size_t)(wc * 16 + i) * N_RULES + r]);
                sm_red[wc * 32 + (tid & 31)] = o;
            }
            __syncthreads();
            if (tid < 32) {
                uint32_t o = sm_red[tid] | sm_red[32 + tid] | sm_red[64 + tid] |
                             sm_red[96 + tid] | sm_red[128 + tid] |
                             sm_red[160 + tid] | sm_red[192 + tid] |
                             sm_red[224 + tid];
                s_w[tid]   = o;
                s_val[tid] = (o == 0u) ? 1.0f : 0.0f;
                uint32_t any = __reduce_or_sync(0xFFFFFFFFu, o);
                if (tid == 0) *s_flag = (any == 0u) ? 1u : 0u;
            }
            __syncthreads();

            bool empty  = (*s_flag != 0u);
            int  chunk  = tid & 7;             // float4 chunk within 32 rules
            int  rowoff = tid >> 3;            // 0..31
            float4 v0 = *reinterpret_cast<const float4*>(s_val + chunk * 4);
            float4* o4 = reinterpret_cast<float4*>(out);
#pragma unroll
            for (int it = 0; it < 16; it++) {
                int b = b0 + it * 32 + rowoff;
                float4 o;
                if (empty) {
                    o = v0;                    // dominant path: all rules empty
                } else {
                    int r0 = rg * 32 + chunk * 4;
                    o.x = (s_w[chunk*4+0] == 0u) ? 1.0f : conj_direct(x, b, r0+0);
                    o.y = (s_w[chunk*4+1] == 0u) ? 1.0f : conj_direct(x, b, r0+1);
                    o.z = (s_w[chunk*4+2] == 0u) ? 1.0f : conj_direct(x, b, r0+2);
                    o.w = (s_w[chunk*4+3] == 0u) ? 1.0f : conj_direct(x, b, r0+3);
                }
                o4[(size_t)b * 512 + rg * 8 + chunk] = o;
            }
        }
    }
}

// Trailing reset: zero the 8 group counters so every graph replay starts
// clean (kernel boundary provides the memory fence). 1 warp, trivial.
__global__ void reset_kernel() {
    if (threadIdx.x < NBG) g_done[threadIdx.x] = 0u;
}

// ---------------------------------------------------------------------------
extern "C" void kernel_launch(void* const* d_in, const int* in_sizes, int n_in,
                              void* d_out, int out_size) {
    const float* x = (const float*)d_in[0];   // [BATCH, IN_DIM]
    const float* W = (const float*)d_in[1];   // [IN_DIM, N_RULES]
    float* out = (float*)d_out;               // [BATCH, N_RULES]

    (void)in_sizes; (void)n_in; (void)out_size;

    fused_kernel<<<GRID, 256>>>(W, x, out);   // pack ∥ out, single launch
    reset_kernel<<<1, 32>>>();                // replay-determinism
}